// round 6
// baseline (speedup 1.0000x reference)
#include <cuda_runtime.h>

#define N_NODES 20000
#define N_EDGES 50000
#define H 64
#define HH 4096
#define NREG 65
#define EPAD (N_EDGES + NREG * 8)
#define GE 8
#define GROUPS 2
#define SUBIT 4
#define MSG_SLOTS (GROUPS * GE * SUBIT)   // 64 slots per block
#define NPB 32
#define RBLOCKS (N_NODES / NPB)           // 625 k_root blocks

// ---------------- scratch: plain scalar device globals ----------------
__device__ float d_Qbuf[NREG * 2 * HH];   // per region: Q0[4096] then Q1[4096]
__device__ float d_Bs[H];                 // sorted breakpoints
__device__ int   d_regid[N_EDGES];
__device__ int   d_hist[NREG];
__device__ int   d_cursor[NREG];
__device__ int   d_sorted[EPAD];
__device__ float d_part[RBLOCKS * 2 * H]; // per-block BN partials (plain stores)
__device__ float d_sums[2 * H];           // final BN sums (plain stores)

// ---------------- 0a) zero output (harness buffer) ----------------
__global__ void k_zero_out(float* out) {
    int i = blockIdx.x * blockDim.x + threadIdx.x;
    if (i < N_NODES * H) out[i] = 0.0f;
}

// ---------------- 0b) small inits (plain stores) ----------------
__global__ void k_init() {
    int i = blockIdx.x * blockDim.x + threadIdx.x;
    if (i < NREG) { d_hist[i] = 0; d_cursor[i] = 0; }
    if (i < EPAD) d_sorted[i] = -1;
}

// ---------------- 1) breakpoints + rank sort (1 block, 64 thr) -------------
__global__ void k_prep(const float* w1, const float* b1) {
    __shared__ float t[H];
    int k = threadIdx.x;
    float w = w1[k];
    float tb = (w == 0.0f) ? 1e30f : (-b1[k] / w);
    t[k] = tb;
    __syncthreads();
    int rank = 0;
    for (int j = 0; j < H; j++) {
        float tj = t[j];
        rank += (tj < tb) || (tj == tb && j < k);
    }
    d_Bs[rank] = tb;
}

// ---------------- 2) per-region Q0/Q1 (65 blocks x 256 thr, scalar) --------
__global__ void k_q(const float* w1, const float* b1,
                    const float* b2, const float* w2) {
    int r = blockIdx.x;
    __shared__ float wk[H], bk[H];
    if (threadIdx.x < H) {
        int k = threadIdx.x;
        float ar;
        if (r == 0)              ar = d_Bs[0] - 1.0f;
        else if (r == NREG - 1)  ar = d_Bs[H - 1] + 1.0f;
        else                     ar = 0.5f * d_Bs[r - 1] + 0.5f * d_Bs[r];
        float w = w1[k], b = b1[k];
        bool act = (ar * w + b) > 0.0f;
        wk[k] = act ? w : 0.0f;
        bk[k] = act ? b : 0.0f;
    }
    __syncthreads();
    int qbase = r * (2 * HH);
    for (int m = threadIdx.x; m < HH; m += blockDim.x) {
        float q0 = b2[m];
        float q1 = 0.0f;
        #pragma unroll 8
        for (int k = 0; k < H; k++) {
            float v = w2[m * H + k];
            q0 = fmaf(bk[k], v, q0);
            q1 = fmaf(wk[k], v, q1);
        }
        d_Qbuf[qbase + m]      = q0;
        d_Qbuf[qbase + HH + m] = q1;
    }
}

// ---------------- 3) region id per edge + histogram (int atomics) ----------
__global__ void k_region(const float* ea) {
    __shared__ float Bs[H];
    __shared__ int bh[NREG];
    int t = threadIdx.x;
    if (t < H) Bs[t] = d_Bs[t];
    if (t < NREG) bh[t] = 0;
    __syncthreads();
    int e = blockIdx.x * blockDim.x + t;
    if (e < N_EDGES) {
        float a = ea[e];
        int r = 0;
        #pragma unroll 8
        for (int k = 0; k < H; k++) r += (Bs[k] <= a) ? 1 : 0;
        d_regid[e] = r;
        atomicAdd(&bh[r], 1);
    }
    __syncthreads();
    if (t < NREG && bh[t] > 0) atomicAdd(&d_hist[t], bh[t]);
}

// ---------------- 4) aligned offsets (1 block / 32 thr, lane 0 serial) -----
__global__ void k_offsets() {
    if (threadIdx.x == 0) {
        int s = 0;
        for (int r = 0; r < NREG; r++) {
            d_cursor[r] = s;
            s += (d_hist[r] + 7) & ~7;
        }
    }
}

// ---------------- 5) scatter edges into region-sorted list (int atomics) ---
__global__ void k_scatter() {
    int e = blockIdx.x * blockDim.x + threadIdx.x;
    if (e < N_EDGES) {
        int r = d_regid[e];
        int pos = atomicAdd(&d_cursor[r], 1);
        d_sorted[pos] = e;
    }
}

// ---------------- 6) message + scatter-add into out (hot kernel) -----------
// edge_index is int32 (JAX default x64-disabled downcasts int64 -> int32).
__global__ void k_msg(const float* x, const float* ea,
                      const int* ei, float* out) {
    __shared__ float xs[GROUPS][GE][H];
    __shared__ float sa[GROUPS][GE];
    __shared__ int   sdst[GROUPS][GE];
    __shared__ int   ssrc[GROUPS][GE];
    __shared__ int   sreg[GROUPS][GE];

    int g = threadIdx.x >> 6;
    int o = threadIdx.x & 63;
    int blockBase = blockIdx.x * MSG_SLOTS;

    for (int it = 0; it < SUBIT; it++) {
        int sbase = blockBase + (it * GROUPS + g) * GE;
        __syncthreads();
        if (o < GE) {
            int slot = sbase + o;
            int eid = (slot < EPAD) ? d_sorted[slot] : -1;
            int src = -1, dst = 0, r = -1;
            float a = 0.0f;
            if (eid >= 0) {
                a = ea[eid];
                src = ei[eid];
                dst = ei[N_EDGES + eid];
                r = d_regid[eid];
                // defensive clamp: never form a wild pointer
                if (src < 0 || src >= N_NODES || dst < 0 || dst >= N_NODES) {
                    src = -1; dst = 0;
                }
            }
            sa[g][o] = a; ssrc[g][o] = src; sdst[g][o] = dst; sreg[g][o] = r;
        }
        __syncthreads();
        int rr = -1;
        #pragma unroll
        for (int j = 0; j < GE; j++) {
            int s = ssrc[g][j];
            xs[g][j][o] = (s >= 0) ? x[s * H + o] : 0.0f;
            int rg = sreg[g][j];
            rr = (rg > rr) ? rg : rr;
        }
        __syncthreads();
        if (rr >= 0) {
            int q0base = rr * (2 * HH);
            int q1base = q0base + HH;
            float acc0[GE], acc1[GE];
            #pragma unroll
            for (int j = 0; j < GE; j++) { acc0[j] = 0.0f; acc1[j] = 0.0f; }
            #pragma unroll 4
            for (int i = 0; i < H; i++) {
                float q0 = d_Qbuf[q0base + i * H + o];
                float q1 = d_Qbuf[q1base + i * H + o];
                #pragma unroll
                for (int j = 0; j < GE; j++) {
                    float xv = xs[g][j][i];
                    acc0[j] = fmaf(xv, q0, acc0[j]);
                    acc1[j] = fmaf(xv, q1, acc1[j]);
                }
            }
            #pragma unroll
            for (int j = 0; j < GE; j++) {
                if (ssrc[g][j] >= 0) {
                    atomicAdd(&out[sdst[g][j] * H + o],
                              fmaf(sa[g][j], acc1[j], acc0[j]));
                }
            }
        }
    }
}

// ---------------- 7) root GEMM + bias + agg(out); partial sums (no atomics)
__global__ void k_root(const float* x, const float* rw,
                       const float* cb, float* out) {
    __shared__ float rws[HH];       // transposed root_w: rws[i*64+o]
    __shared__ float xrs[4][H];
    __shared__ float red[256];
    int t = threadIdx.x;
    for (int idx = t; idx < HH; idx += 256) {
        int oo = idx >> 6, ii = idx & 63;
        rws[ii * H + oo] = rw[idx];
    }
    int o = t & 63, nl = t >> 6;
    __syncthreads();
    float cbo = cb[o];
    float psum = 0.0f, psq = 0.0f;
    int n0 = blockIdx.x * NPB;
    for (int c = 0; c < NPB; c += 4) {
        int n = n0 + c + nl;
        xrs[nl][o] = x[n * H + o];
        __syncthreads();
        float acc = 0.0f;
        #pragma unroll 8
        for (int i = 0; i < H; i++) acc = fmaf(xrs[nl][i], rws[i * H + o], acc);
        float val = acc + out[n * H + o] + cbo;
        out[n * H + o] = val;
        psum += val;
        psq = fmaf(val, val, psq);
        __syncthreads();
    }
    red[t] = psum; __syncthreads();
    if (nl < 2) red[t] += red[t + 128];
    __syncthreads();
    if (nl == 0) d_part[blockIdx.x * (2 * H) + o] = red[t] + red[t + 64];
    __syncthreads();
    red[t] = psq; __syncthreads();
    if (nl < 2) red[t] += red[t + 128];
    __syncthreads();
    if (nl == 0) d_part[blockIdx.x * (2 * H) + H + o] = red[t] + red[t + 64];
}

// ---------------- 8) reduce partials (1 block, 128 thr, plain stores) ------
__global__ void k_stats() {
    int t = threadIdx.x;   // 0..127: [0:64) sums, [64:128) sumsq
    float s = 0.0f;
    for (int b = 0; b < RBLOCKS; b++) s += d_part[b * (2 * H) + t];
    d_sums[t] = s;
}

// ---------------- 9) BN + relu + residual ----------------
__global__ void k_fin(const float* x, const float* gamma,
                      const float* beta, float* out) {
    int idx = blockIdx.x * blockDim.x + threadIdx.x;
    if (idx < N_NODES * H) {
        int o = idx & 63;
        const float invN = 1.0f / (float)N_NODES;
        float mean = d_sums[o] * invN;
        float var  = d_sums[H + o] * invN - mean * mean;
        float istd = rsqrtf(var + 1e-5f);
        float v = out[idx];
        float bn = fmaf((v - mean) * istd, gamma[o], beta[o]);
        out[idx] = x[idx] + fmaxf(bn, 0.0f);
    }
}

extern "C" void kernel_launch(void* const* d_in, const int* in_sizes, int n_in,
                              void* d_out, int out_size) {
    const float* x     = (const float*)d_in[0];
    const float* ea    = (const float*)d_in[1];
    const int*   ei    = (const int*)d_in[2];      // int32 edge_index
    const float* w1    = (const float*)d_in[3];
    const float* b1    = (const float*)d_in[4];
    const float* w2    = (const float*)d_in[5];
    const float* b2    = (const float*)d_in[6];
    const float* rw    = (const float*)d_in[7];
    const float* cb    = (const float*)d_in[8];
    const float* gamma = (const float*)d_in[9];
    const float* beta  = (const float*)d_in[10];
    float* out = (float*)d_out;

    k_zero_out<<<(N_NODES * H + 255) / 256, 256>>>(out);
    k_init<<<(EPAD + 255) / 256, 256>>>();
    k_prep<<<1, 64>>>(w1, b1);
    k_q<<<NREG, 256>>>(w1, b1, b2, w2);
    k_region<<<(N_EDGES + 255) / 256, 256>>>(ea);
    k_offsets<<<1, 32>>>();
    k_scatter<<<(N_EDGES + 255) / 256, 256>>>();
    k_msg<<<(EPAD + MSG_SLOTS - 1) / MSG_SLOTS, 128>>>(x, ea, ei, out);
    k_root<<<RBLOCKS, 256>>>(x, rw, cb, out);
    k_stats<<<1, 128>>>();
    k_fin<<<(N_NODES * H + 255) / 256, 256>>>(x, gamma, beta, out);
}

// round 7
// speedup vs baseline: 1.9135x; 1.9135x over previous
#include <cuda_runtime.h>

#define N_NODES 20000
#define N_EDGES 50000
#define H 64
#define HH 4096
#define NREG 65
#define GE 16
#define GROUPS 2
#define SUBIT 4
#define MSG_SLOTS (GROUPS * GE * SUBIT)   // 128 slots per block
#define EPAD (N_EDGES + NREG * GE)
#define NPB 32
#define RBLOCKS (N_NODES / NPB)           // 625 k_root blocks

// ---------------- scratch: plain scalar device globals ----------------
__device__ float d_Qbuf[NREG * 2 * HH];   // per region: Q0[4096] then Q1[4096]
__device__ float d_Bs[H];                 // sorted breakpoints
__device__ int   d_Bidx[H];               // neuron index per rank
__device__ int   d_regid[N_EDGES];
__device__ int   d_hist[NREG];
__device__ int   d_cursor[NREG];
__device__ int   d_sorted[EPAD];
__device__ float d_part[RBLOCKS * 2 * H]; // per-block BN partials
__device__ float d_sums[2 * H];           // final BN sums

// ---------------- 0a) zero output (harness buffer) ----------------
__global__ void k_zero_out(float* out) {
    int i = blockIdx.x * blockDim.x + threadIdx.x;
    if (i < N_NODES * H) out[i] = 0.0f;
}

// ---------------- 0b) small inits ----------------
__global__ void k_init() {
    int i = blockIdx.x * blockDim.x + threadIdx.x;
    if (i < NREG) { d_hist[i] = 0; d_cursor[i] = 0; }
    if (i < EPAD) d_sorted[i] = -1;
}

// ---------------- 1) breakpoints + rank sort (1 block, 64 thr) -------------
__global__ void k_prep(const float* w1, const float* b1) {
    __shared__ float t[H];
    int k = threadIdx.x;
    float w = w1[k];
    float tb = (w == 0.0f) ? 1e30f : (-b1[k] / w);
    t[k] = tb;
    __syncthreads();
    int rank = 0;
    for (int j = 0; j < H; j++) {
        float tj = t[j];
        rank += (tj < tb) || (tj == tb && j < k);
    }
    d_Bs[rank] = tb;
    d_Bidx[rank] = k;
}

// ---------------- 2) Q0/Q1 via rank-1 incremental updates ------------------
// 32 blocks x 128 thr; thread -> one m. w2 rows staged in padded shared.
__global__ void __launch_bounds__(128) k_q(const float* w1, const float* b1,
                                           const float* b2, const float* w2) {
    __shared__ float w2sh[128][H + 1];   // +1 pad: conflict-free column reads
    __shared__ float m0b[H], m0w[H];     // region-0 masked b1/w1
    __shared__ float dB[H], dW[H];       // per-rank deltas
    __shared__ int   cix[H];             // per-rank neuron column

    int t = threadIdx.x;
    int mbase = blockIdx.x * 128;

    // stage w2 rows [mbase, mbase+128) coalesced
    for (int i = t; i < 128 * H; i += 128) {
        int ml = i >> 6, k = i & 63;
        w2sh[ml][k] = w2[(mbase + ml) * H + k];
    }
    if (t < H) {
        int k = t;
        float w = w1[k], b = b1[k];
        // region 0 (a below all breakpoints): active iff w<0, or w==0 && b>0
        bool act0 = (w < 0.0f) || (w == 0.0f && b > 0.0f);
        m0b[k] = act0 ? b : 0.0f;
        m0w[k] = act0 ? w : 0.0f;
        // crossing rank r flips neuron d_Bidx[r]: ON if w>0 (+), OFF if w<0 (-)
        int kr = d_Bidx[t];
        float wr = w1[kr], br = b1[kr];
        float sgn = (wr > 0.0f) ? 1.0f : -1.0f;
        dB[t] = sgn * br;
        dW[t] = sgn * wr;
        cix[t] = kr;
    }
    __syncthreads();

    int m = mbase + t;
    const float* row = w2sh[t];
    float q0 = b2[m];
    float q1 = 0.0f;
    #pragma unroll 8
    for (int k = 0; k < H; k++) {
        float v = row[k];
        q0 = fmaf(m0b[k], v, q0);
        q1 = fmaf(m0w[k], v, q1);
    }
    #pragma unroll 4
    for (int r = 0; r < NREG; r++) {
        d_Qbuf[r * (2 * HH) + m]      = q0;
        d_Qbuf[r * (2 * HH) + HH + m] = q1;
        if (r < H) {
            float v = row[cix[r]];
            q0 = fmaf(dB[r], v, q0);
            q1 = fmaf(dW[r], v, q1);
        }
    }
}

// ---------------- 3) region id per edge + histogram ----------------
__global__ void k_region(const float* ea) {
    __shared__ float Bs[H];
    __shared__ int bh[NREG];
    int t = threadIdx.x;
    if (t < H) Bs[t] = d_Bs[t];
    if (t < NREG) bh[t] = 0;
    __syncthreads();
    int e = blockIdx.x * blockDim.x + t;
    if (e < N_EDGES) {
        float a = ea[e];
        int r = 0;
        #pragma unroll 8
        for (int k = 0; k < H; k++) r += (Bs[k] <= a) ? 1 : 0;
        d_regid[e] = r;
        atomicAdd(&bh[r], 1);
    }
    __syncthreads();
    if (t < NREG && bh[t] > 0) atomicAdd(&d_hist[t], bh[t]);
}

// ---------------- 4) GE-aligned offsets ----------------
__global__ void k_offsets() {
    if (threadIdx.x == 0) {
        int s = 0;
        for (int r = 0; r < NREG; r++) {
            d_cursor[r] = s;
            s += (d_hist[r] + (GE - 1)) & ~(GE - 1);
        }
    }
}

// ---------------- 5) scatter edges into region-sorted list ----------------
__global__ void k_scatter() {
    int e = blockIdx.x * blockDim.x + threadIdx.x;
    if (e < N_EDGES) {
        int r = d_regid[e];
        int pos = atomicAdd(&d_cursor[r], 1);
        d_sorted[pos] = e;
    }
}

// ---------------- 6) message + scatter-add into out (hot kernel) -----------
__global__ void __launch_bounds__(128) k_msg(const float* x, const float* ea,
                                             const int* ei, float* out) {
    __shared__ float xs[GROUPS][GE][H];
    __shared__ float sa[GROUPS][GE];
    __shared__ int   sdst[GROUPS][GE];
    __shared__ int   ssrc[GROUPS][GE];
    __shared__ int   sreg[GROUPS][GE];

    int g = threadIdx.x >> 6;
    int o = threadIdx.x & 63;
    int blockBase = blockIdx.x * MSG_SLOTS;

    for (int it = 0; it < SUBIT; it++) {
        int sbase = blockBase + (it * GROUPS + g) * GE;
        __syncthreads();
        if (o < GE) {
            int slot = sbase + o;
            int eid = (slot < EPAD) ? d_sorted[slot] : -1;
            int src = -1, dst = 0, r = -1;
            float a = 0.0f;
            if (eid >= 0) {
                a = ea[eid];
                src = ei[eid];
                dst = ei[N_EDGES + eid];
                r = d_regid[eid];
                if (src < 0 || src >= N_NODES || dst < 0 || dst >= N_NODES) {
                    src = -1; dst = 0;
                }
            }
            sa[g][o] = a; ssrc[g][o] = src; sdst[g][o] = dst; sreg[g][o] = r;
        }
        __syncthreads();
        int rr = -1;
        #pragma unroll
        for (int j = 0; j < GE; j++) {
            int s = ssrc[g][j];
            xs[g][j][o] = (s >= 0) ? x[s * H + o] : 0.0f;
            int rg = sreg[g][j];
            rr = (rg > rr) ? rg : rr;
        }
        __syncthreads();
        if (rr >= 0) {
            int q0base = rr * (2 * HH);
            int q1base = q0base + HH;
            float acc0[GE], acc1[GE];
            #pragma unroll
            for (int j = 0; j < GE; j++) { acc0[j] = 0.0f; acc1[j] = 0.0f; }
            #pragma unroll 4
            for (int i = 0; i < H; i++) {
                float q0 = d_Qbuf[q0base + i * H + o];
                float q1 = d_Qbuf[q1base + i * H + o];
                #pragma unroll
                for (int j = 0; j < GE; j++) {
                    float xv = xs[g][j][i];
                    acc0[j] = fmaf(xv, q0, acc0[j]);
                    acc1[j] = fmaf(xv, q1, acc1[j]);
                }
            }
            #pragma unroll
            for (int j = 0; j < GE; j++) {
                if (ssrc[g][j] >= 0) {
                    atomicAdd(&out[sdst[g][j] * H + o],
                              fmaf(sa[g][j], acc1[j], acc0[j]));
                }
            }
        }
    }
}

// ---------------- 7) root GEMM + bias + agg(out); BN partials --------------
__global__ void k_root(const float* x, const float* rw,
                       const float* cb, float* out) {
    __shared__ float rws[HH];
    __shared__ float xrs[4][H];
    __shared__ float red[256];
    int t = threadIdx.x;
    for (int idx = t; idx < HH; idx += 256) {
        int oo = idx >> 6, ii = idx & 63;
        rws[ii * H + oo] = rw[idx];
    }
    int o = t & 63, nl = t >> 6;
    __syncthreads();
    float cbo = cb[o];
    float psum = 0.0f, psq = 0.0f;
    int n0 = blockIdx.x * NPB;
    for (int c = 0; c < NPB; c += 4) {
        int n = n0 + c + nl;
        xrs[nl][o] = x[n * H + o];
        __syncthreads();
        float acc = 0.0f;
        #pragma unroll 8
        for (int i = 0; i < H; i++) acc = fmaf(xrs[nl][i], rws[i * H + o], acc);
        float val = acc + out[n * H + o] + cbo;
        out[n * H + o] = val;
        psum += val;
        psq = fmaf(val, val, psq);
        __syncthreads();
    }
    red[t] = psum; __syncthreads();
    if (nl < 2) red[t] += red[t + 128];
    __syncthreads();
    if (nl == 0) d_part[blockIdx.x * (2 * H) + o] = red[t] + red[t + 64];
    __syncthreads();
    red[t] = psq; __syncthreads();
    if (nl < 2) red[t] += red[t + 128];
    __syncthreads();
    if (nl == 0) d_part[blockIdx.x * (2 * H) + H + o] = red[t] + red[t + 64];
}

// ---------------- 8) reduce partials (1 block, 128 thr) ----------------
__global__ void k_stats() {
    int t = threadIdx.x;
    float s = 0.0f;
    for (int b = 0; b < RBLOCKS; b++) s += d_part[b * (2 * H) + t];
    d_sums[t] = s;
}

// ---------------- 9) BN + relu + residual ----------------
__global__ void k_fin(const float* x, const float* gamma,
                      const float* beta, float* out) {
    int idx = blockIdx.x * blockDim.x + threadIdx.x;
    if (idx < N_NODES * H) {
        int o = idx & 63;
        const float invN = 1.0f / (float)N_NODES;
        float mean = d_sums[o] * invN;
        float var  = d_sums[H + o] * invN - mean * mean;
        float istd = rsqrtf(var + 1e-5f);
        float v = out[idx];
        float bn = fmaf((v - mean) * istd, gamma[o], beta[o]);
        out[idx] = x[idx] + fmaxf(bn, 0.0f);
    }
}

extern "C" void kernel_launch(void* const* d_in, const int* in_sizes, int n_in,
                              void* d_out, int out_size) {
    const float* x     = (const float*)d_in[0];
    const float* ea    = (const float*)d_in[1];
    const int*   ei    = (const int*)d_in[2];      // int32 edge_index
    const float* w1    = (const float*)d_in[3];
    const float* b1    = (const float*)d_in[4];
    const float* w2    = (const float*)d_in[5];
    const float* b2    = (const float*)d_in[6];
    const float* rw    = (const float*)d_in[7];
    const float* cb    = (const float*)d_in[8];
    const float* gamma = (const float*)d_in[9];
    const float* beta  = (const float*)d_in[10];
    float* out = (float*)d_out;

    k_zero_out<<<(N_NODES * H + 255) / 256, 256>>>(out);
    k_init<<<(EPAD + 255) / 256, 256>>>();
    k_prep<<<1, 64>>>(w1, b1);
    k_q<<<HH / 128, 128>>>(w1, b1, b2, w2);
    k_region<<<(N_EDGES + 255) / 256, 256>>>(ea);
    k_offsets<<<1, 32>>>();
    k_scatter<<<(N_EDGES + 255) / 256, 256>>>();
    k_msg<<<(EPAD + MSG_SLOTS - 1) / MSG_SLOTS, 128>>>(x, ea, ei, out);
    k_root<<<RBLOCKS, 256>>>(x, rw, cb, out);
    k_stats<<<1, 128>>>();
    k_fin<<<(N_NODES * H + 255) / 256, 256>>>(x, gamma, beta, out);
}